// round 1
// baseline (speedup 1.0000x reference)
#include <cuda_runtime.h>
#include <math.h>

// ----------------------------------------------------------------------------
// Causal scaled-dot-product attention, fp32 SIMT baseline.
//   N=64 (batch*heads), T=1024 (seq), D=64 (head dim)
//   scores = QK^T / 8, key-padding mask (|K|-sum == 0), causal mask,
//   softmax, O = P V.
// Block: 64 queries of one batch. 256 threads as 16x16, 4x4 micro-tiles.
// Online softmax over key tiles of 64; only tiles kt <= qt are touched.
// Shared: Q^T, K^T (reused for P^T), V  -- transposed layouts so GEMM
// inner-loop float4 loads are contiguous (bank-conflict-free).
// ----------------------------------------------------------------------------

namespace {
constexpr int kN = 64;
constexpr int kT = 1024;
constexpr int kD = 64;
constexpr int BM = 64;   // query rows per block
constexpr int BN = 64;   // keys per tile
constexpr int STRIDE = 68;  // padded shared row stride (floats), float4-aligned
constexpr float kScale = 0.125f;              // 1/sqrt(64)
constexpr float kPad = -4294967295.0f;        // -2^32 + 1
constexpr int kThreads = 256;
constexpr int kSmemFloats = 3 * kD * STRIDE + BN;  // QT + KT/PT + V + flags
}  // namespace

__global__ __launch_bounds__(kThreads)
void attn_fp32_kernel(const float* __restrict__ Q,
                      const float* __restrict__ K,
                      const float* __restrict__ V,
                      float* __restrict__ O) {
    extern __shared__ float smem[];
    float* sQT    = smem;                  // [D][STRIDE] : Q^T[d][r], pre-scaled
    float* sKT    = sQT + kD * STRIDE;     // [D][STRIDE] : K^T[d][c]; reused as P^T[c][r]
    float* sV     = sKT + kD * STRIDE;     // [BN][STRIDE]: V[k][d]
    float* sFlags = sV + kD * STRIDE;      // [BN]        : per-key |K| row sums

    const int tid = threadIdx.x;
    const int ty = tid >> 4;     // 0..15
    const int tx = tid & 15;     // 0..15
    // heavy q-tiles first (qt=15 does 16 key tiles) for better tail balance
    const int qt = (kT / BM - 1) - blockIdx.x;
    const int n  = blockIdx.y;
    const int q0 = qt * BM;

    const float* Qg = Q + ((size_t)n * kT + q0) * kD;
    const float* Kg = K + (size_t)n * kT * kD;
    const float* Vg = V + (size_t)n * kT * kD;

    // ---- load Q tile, transposed + pre-scaled -------------------------------
#pragma unroll
    for (int i = 0; i < 4; i++) {
        const int r = ty + 16 * i;                      // row within tile
        float4 qv = *(const float4*)(Qg + r * kD + 4 * tx);
        const int d = 4 * tx;
        sQT[(d + 0) * STRIDE + r] = qv.x * kScale;
        sQT[(d + 1) * STRIDE + r] = qv.y * kScale;
        sQT[(d + 2) * STRIDE + r] = qv.z * kScale;
        sQT[(d + 3) * STRIDE + r] = qv.w * kScale;
    }

    float m_i[4], l_i[4], o_acc[4][4];
#pragma unroll
    for (int i = 0; i < 4; i++) {
        m_i[i] = -INFINITY;
        l_i[i] = 0.f;
#pragma unroll
        for (int j = 0; j < 4; j++) o_acc[i][j] = 0.f;
    }

    const float* qptr = sQT + 4 * ty;
    const float* kptr = sKT + 4 * tx;
    const float* pptr = sKT + 4 * ty;   // P^T view after reuse
    const float* vptr = sV + 4 * tx;

    for (int kt = 0; kt <= qt; kt++) {
        const int k0 = kt * BN;
        __syncthreads();  // prior PV finished reading sKT/sV before overwrite

        // ---- load K (transposed) + key-validity flags + V -------------------
#pragma unroll
        for (int i = 0; i < 4; i++) {
            const int r = ty + 16 * i;
            float4 kv = *(const float4*)(Kg + (size_t)(k0 + r) * kD + 4 * tx);
            const int d = 4 * tx;
            sKT[(d + 0) * STRIDE + r] = kv.x;
            sKT[(d + 1) * STRIDE + r] = kv.y;
            sKT[(d + 2) * STRIDE + r] = kv.z;
            sKT[(d + 3) * STRIDE + r] = kv.w;
            float asum = fabsf(kv.x) + fabsf(kv.y) + fabsf(kv.z) + fabsf(kv.w);
#pragma unroll
            for (int off = 8; off > 0; off >>= 1)
                asum += __shfl_xor_sync(0xffffffffu, asum, off, 16);
            if (tx == 0) sFlags[r] = asum;
            float4 vv = *(const float4*)(Vg + (size_t)(k0 + r) * kD + 4 * tx);
            *(float4*)(sV + r * STRIDE + 4 * tx) = vv;
        }
        __syncthreads();

        // ---- S = (Q*scale) K^T ---------------------------------------------
        float acc[4][4];
#pragma unroll
        for (int i = 0; i < 4; i++)
#pragma unroll
            for (int j = 0; j < 4; j++) acc[i][j] = 0.f;

#pragma unroll 16
        for (int k = 0; k < kD; k++) {
            float4 a4 = *(const float4*)(qptr + k * STRIDE);
            float4 b4 = *(const float4*)(kptr + k * STRIDE);
            const float av[4] = {a4.x, a4.y, a4.z, a4.w};
            const float bv[4] = {b4.x, b4.y, b4.z, b4.w};
#pragma unroll
            for (int i = 0; i < 4; i++)
#pragma unroll
                for (int j = 0; j < 4; j++) acc[i][j] += av[i] * bv[j];
        }

        // ---- masks ----------------------------------------------------------
        const bool diag = (kt == qt);
        float flg[4];
#pragma unroll
        for (int j = 0; j < 4; j++) flg[j] = sFlags[4 * tx + j];
#pragma unroll
        for (int i = 0; i < 4; i++) {
            const int r = 4 * ty + i;
#pragma unroll
            for (int j = 0; j < 4; j++) {
                const int c = 4 * tx + j;
                float s = acc[i][j];
                if (flg[j] == 0.f) s = kPad;       // padded key
                if (diag && c > r) s = kPad;       // future key
                acc[i][j] = s;
            }
        }

        // ---- online softmax update -----------------------------------------
#pragma unroll
        for (int i = 0; i < 4; i++) {
            float rmax = fmaxf(fmaxf(acc[i][0], acc[i][1]),
                               fmaxf(acc[i][2], acc[i][3]));
#pragma unroll
            for (int off = 8; off > 0; off >>= 1)
                rmax = fmaxf(rmax, __shfl_xor_sync(0xffffffffu, rmax, off, 16));
            const float mnew = fmaxf(m_i[i], rmax);
            const float corr = __expf(m_i[i] - mnew);  // 0 when m_i == -inf
            float rsum = 0.f;
#pragma unroll
            for (int j = 0; j < 4; j++) {
                const float p = __expf(acc[i][j] - mnew);
                acc[i][j] = p;
                rsum += p;
            }
#pragma unroll
            for (int off = 8; off > 0; off >>= 1)
                rsum += __shfl_xor_sync(0xffffffffu, rsum, off, 16);
            l_i[i] = l_i[i] * corr + rsum;
            m_i[i] = mnew;
#pragma unroll
            for (int j = 0; j < 4; j++) o_acc[i][j] *= corr;
        }

        __syncthreads();  // everyone done reading K from sKT
        // ---- stage P^T into the K buffer -----------------------------------
#pragma unroll
        for (int i = 0; i < 4; i++)
#pragma unroll
            for (int j = 0; j < 4; j++)
                sKT[(4 * tx + j) * STRIDE + 4 * ty + i] = acc[i][j];
        __syncthreads();

        // ---- O += P V -------------------------------------------------------
#pragma unroll 16
        for (int k = 0; k < BN; k++) {
            float4 p4 = *(const float4*)(pptr + k * STRIDE);   // P^T[k][4ty..]
            float4 v4 = *(const float4*)(vptr + k * STRIDE);   // V[k][4tx..]
            const float pv[4] = {p4.x, p4.y, p4.z, p4.w};
            const float vv[4] = {v4.x, v4.y, v4.z, v4.w};
#pragma unroll
            for (int i = 0; i < 4; i++)
#pragma unroll
                for (int j = 0; j < 4; j++) o_acc[i][j] += pv[i] * vv[j];
        }
    }

    // ---- finalize: divide by l, store --------------------------------------
    float* Og = O + ((size_t)n * kT + q0) * kD;
#pragma unroll
    for (int i = 0; i < 4; i++) {
        const float inv = 1.f / l_i[i];
        float4 res;
        res.x = o_acc[i][0] * inv;
        res.y = o_acc[i][1] * inv;
        res.z = o_acc[i][2] * inv;
        res.w = o_acc[i][3] * inv;
        *(float4*)(Og + (size_t)(4 * ty + i) * kD + 4 * tx) = res;
    }
}

extern "C" void kernel_launch(void* const* d_in, const int* in_sizes, int n_in,
                              void* d_out, int out_size) {
    const float* q = (const float*)d_in[0];
    const float* k = (const float*)d_in[1];
    const float* v = (const float*)d_in[2];
    float* o = (float*)d_out;

    const size_t smem_bytes = (size_t)kSmemFloats * sizeof(float);  // ~52.5 KB
    // Idempotent, deterministic, not stream-ordered: safe under graph capture.
    cudaFuncSetAttribute(attn_fp32_kernel,
                         cudaFuncAttributeMaxDynamicSharedMemorySize,
                         (int)smem_bytes);

    dim3 grid(kT / BM, kN);  // 16 x 64 = 1024 blocks
    attn_fp32_kernel<<<grid, kThreads, smem_bytes>>>(q, k, v, o);
}

// round 3
// speedup vs baseline: 3.2127x; 3.2127x over previous
#include <cuda_runtime.h>
#include <math.h>
#include <stdint.h>

// ----------------------------------------------------------------------------
// Causal masked softmax attention, tf32 tensor-core flash kernel.
//   N=64, T=1024, D=64.  scores = QK^T/8 (+key-pad mask, causal), softmax, PV.
// Block: 64 queries of one batch, 4 warps (each 16 query rows), BN=64 key tiles.
// mma.sync.m16n8k8.tf32: Q fragments register-resident; K/V tf32-rounded in
// shared; P staged through a per-warp shared region for the PV re-fragment.
// All inner-loop LDS patterns are bank-conflict-free by stride choice.
// ----------------------------------------------------------------------------

namespace {
constexpr int kT = 1024;
constexpr int kD = 64;
constexpr int BM = 64;
constexpr int BN = 64;
constexpr int THREADS = 128;
constexpr int STRK = 68;   // sK stride: B-load banks (4g+tig) -> bijective
constexpr int STRV = 72;   // sV stride: B-load banks (8tig+g) -> bijective
constexpr int STRP = 68;   // sQ/sP stride: A-load banks (4g+tig) -> bijective
constexpr float kQScale = 0.18033688011112042f;  // (1/8) * log2(e)
constexpr float kPad = -1e30f;                   // exp2 -> 0, same as ref PAD
constexpr int SM_K = 0;
constexpr int SM_V = BN * STRK;
constexpr int SM_P = SM_V + BN * STRV;
constexpr int SM_F = SM_P + BM * STRP;
constexpr int SMEM_FLOATS = SM_F + BN;           // ~53.5 KB
}  // namespace

__device__ __forceinline__ float ex2f(float x) {
    float r; asm("ex2.approx.ftz.f32 %0, %1;" : "=f"(r) : "f"(x)); return r;
}
__device__ __forceinline__ float tf32r(float x) {
    uint32_t u; asm("cvt.rna.tf32.f32 %0, %1;" : "=r"(u) : "f"(x));
    return __uint_as_float(u);
}
__device__ __forceinline__ void mma_tf32(float (&d)[4],
                                         uint32_t a0, uint32_t a1,
                                         uint32_t a2, uint32_t a3,
                                         uint32_t b0, uint32_t b1) {
    asm volatile(
        "mma.sync.aligned.m16n8k8.row.col.f32.tf32.tf32.f32 "
        "{%0,%1,%2,%3}, {%4,%5,%6,%7}, {%8,%9}, {%0,%1,%2,%3};\n"
        : "+f"(d[0]), "+f"(d[1]), "+f"(d[2]), "+f"(d[3])
        : "r"(a0), "r"(a1), "r"(a2), "r"(a3), "r"(b0), "r"(b1));
}

__global__ __launch_bounds__(THREADS)
void attn_tf32_kernel(const float* __restrict__ Q, const float* __restrict__ K,
                      const float* __restrict__ V, float* __restrict__ O) {
    extern __shared__ float sm[];
    float* sK = sm + SM_K;   // [BN][STRK]  keys row-major (tf32-rounded)
    float* sV = sm + SM_V;   // [BN][STRV]  V row-major (tf32-rounded)
    float* sP = sm + SM_P;   // [BM][STRP]  Q staging, then per-warp P
    float* sF = sm + SM_F;   // [BN]        per-key |K| row sums

    const int tid = threadIdx.x;
    const int warp = tid >> 5;
    const int lane = tid & 31;
    const int g = lane >> 2;     // groupID 0..7
    const int tig = lane & 3;    // thread-in-group 0..3
    const int qt = (kT / BM - 1) - blockIdx.x;   // heavy tiles first
    const int bn = blockIdx.y;
    const int q0 = qt * BM;

    const float* Qg = Q + ((size_t)bn * kT + q0) * kD;
    const float* Kg = K + (size_t)bn * kT * kD;
    const float* Vg = V + (size_t)bn * kT * kD;

    // ---- stage Q (scaled, tf32-rounded) into the sP region ------------------
    {
        const int tx = tid & 15, ty = tid >> 4;
#pragma unroll
        for (int i = 0; i < 8; i++) {
            const int r = ty + 8 * i;
            float4 qv = *(const float4*)(Qg + r * kD + 4 * tx);
            float* dst = sP + r * STRP + 4 * tx;
            dst[0] = tf32r(qv.x * kQScale);
            dst[1] = tf32r(qv.y * kQScale);
            dst[2] = tf32r(qv.z * kQScale);
            dst[3] = tf32r(qv.w * kQScale);
        }
    }
    __syncthreads();

    // ---- Q fragments: register-resident for the whole kernel ----------------
    uint32_t qf[8][4];
    {
        const float* mq = sP + (warp * 16) * STRP;
#pragma unroll
        for (int kb = 0; kb < 8; kb++) {
            qf[kb][0] = __float_as_uint(mq[g * STRP + kb * 8 + tig]);
            qf[kb][1] = __float_as_uint(mq[(g + 8) * STRP + kb * 8 + tig]);
            qf[kb][2] = __float_as_uint(mq[g * STRP + kb * 8 + tig + 4]);
            qf[kb][3] = __float_as_uint(mq[(g + 8) * STRP + kb * 8 + tig + 4]);
        }
    }

    float m0 = kPad, m1 = kPad, l0 = 0.f, l1 = 0.f;
    float o[8][4];
#pragma unroll
    for (int nb = 0; nb < 8; nb++)
#pragma unroll
        for (int j = 0; j < 4; j++) o[nb][j] = 0.f;

    float* sPw = sP + (warp * 16) * STRP;          // warp-private P region
    const int rowg0 = q0 + warp * 16 + g;          // global q row (c0/c1)
    const int rowg1 = rowg0 + 8;                   // global q row (c2/c3)

    for (int kt = 0; kt <= qt; kt++) {
        const int k0 = kt * BN;
        __syncthreads();   // prior PV done with sK/sV before overwrite

        // ---- load K, V (tf32-rounded) + key validity sums -------------------
        {
            const int tx = tid & 15, ty = tid >> 4;
#pragma unroll
            for (int i = 0; i < 8; i++) {
                const int r = ty + 8 * i;
                float4 kv = *(const float4*)(Kg + (size_t)(k0 + r) * kD + 4 * tx);
                float* dk = sK + r * STRK + 4 * tx;
                dk[0] = tf32r(kv.x); dk[1] = tf32r(kv.y);
                dk[2] = tf32r(kv.z); dk[3] = tf32r(kv.w);
                float asum = fabsf(kv.x) + fabsf(kv.y) + fabsf(kv.z) + fabsf(kv.w);
#pragma unroll
                for (int off = 8; off > 0; off >>= 1)
                    asum += __shfl_xor_sync(0xffffffffu, asum, off, 16);
                if (tx == 0) sF[r] = asum;
                float4 vv = *(const float4*)(Vg + (size_t)(k0 + r) * kD + 4 * tx);
                float* dv = sV + r * STRV + 4 * tx;
                dv[0] = tf32r(vv.x); dv[1] = tf32r(vv.y);
                dv[2] = tf32r(vv.z); dv[3] = tf32r(vv.w);
            }
        }
        __syncthreads();

        // ---- S = Q K^T on tensor cores --------------------------------------
        float s[8][4];
#pragma unroll
        for (int nb = 0; nb < 8; nb++)
#pragma unroll
            for (int j = 0; j < 4; j++) s[nb][j] = 0.f;
#pragma unroll
        for (int kb = 0; kb < 8; kb++) {
#pragma unroll
            for (int nb = 0; nb < 8; nb++) {
                const float* kp = sK + (nb * 8 + g) * STRK + kb * 8 + tig;
                mma_tf32(s[nb], qf[kb][0], qf[kb][1], qf[kb][2], qf[kb][3],
                         __float_as_uint(kp[0]), __float_as_uint(kp[4]));
            }
        }

        // ---- masks ----------------------------------------------------------
        const bool diag = (kt == qt);
#pragma unroll
        for (int nb = 0; nb < 8; nb++) {
            const int c = k0 + nb * 8 + 2 * tig;
            const float f0 = sF[nb * 8 + 2 * tig];
            const float f1 = sF[nb * 8 + 2 * tig + 1];
            if (f0 == 0.f) { s[nb][0] = kPad; s[nb][2] = kPad; }
            if (f1 == 0.f) { s[nb][1] = kPad; s[nb][3] = kPad; }
            if (diag) {
                if (c > rowg0)     s[nb][0] = kPad;
                if (c + 1 > rowg0) s[nb][1] = kPad;
                if (c > rowg1)     s[nb][2] = kPad;
                if (c + 1 > rowg1) s[nb][3] = kPad;
            }
        }

        // ---- online softmax (base 2) ----------------------------------------
        float rmax0 = kPad, rmax1 = kPad;
#pragma unroll
        for (int nb = 0; nb < 8; nb++) {
            rmax0 = fmaxf(rmax0, fmaxf(s[nb][0], s[nb][1]));
            rmax1 = fmaxf(rmax1, fmaxf(s[nb][2], s[nb][3]));
        }
        rmax0 = fmaxf(rmax0, __shfl_xor_sync(0xffffffffu, rmax0, 1));
        rmax0 = fmaxf(rmax0, __shfl_xor_sync(0xffffffffu, rmax0, 2));
        rmax1 = fmaxf(rmax1, __shfl_xor_sync(0xffffffffu, rmax1, 1));
        rmax1 = fmaxf(rmax1, __shfl_xor_sync(0xffffffffu, rmax1, 2));
        const float mn0 = fmaxf(m0, rmax0);
        const float mn1 = fmaxf(m1, rmax1);
        const float corr0 = ex2f(m0 - mn0);
        const float corr1 = ex2f(m1 - mn1);
        float rs0 = 0.f, rs1 = 0.f;
#pragma unroll
        for (int nb = 0; nb < 8; nb++) {
            const float p0 = ex2f(s[nb][0] - mn0);
            const float p1 = ex2f(s[nb][1] - mn0);
            const float p2 = ex2f(s[nb][2] - mn1);
            const float p3 = ex2f(s[nb][3] - mn1);
            rs0 += p0 + p1;
            rs1 += p2 + p3;
            *(float2*)(sPw + g * STRP + nb * 8 + 2 * tig) =
                make_float2(tf32r(p0), tf32r(p1));
            *(float2*)(sPw + (g + 8) * STRP + nb * 8 + 2 * tig) =
                make_float2(tf32r(p2), tf32r(p3));
        }
        rs0 += __shfl_xor_sync(0xffffffffu, rs0, 1);
        rs0 += __shfl_xor_sync(0xffffffffu, rs0, 2);
        rs1 += __shfl_xor_sync(0xffffffffu, rs1, 1);
        rs1 += __shfl_xor_sync(0xffffffffu, rs1, 2);
        l0 = l0 * corr0 + rs0; m0 = mn0;
        l1 = l1 * corr1 + rs1; m1 = mn1;
#pragma unroll
        for (int nb = 0; nb < 8; nb++) {
            o[nb][0] *= corr0; o[nb][1] *= corr0;
            o[nb][2] *= corr1; o[nb][3] *= corr1;
        }
        __syncwarp();   // P stores visible to the warp before re-fragmenting

        // ---- O += P V on tensor cores ---------------------------------------
#pragma unroll
        for (int kb = 0; kb < 8; kb++) {
            const uint32_t a0 = __float_as_uint(sPw[g * STRP + kb * 8 + tig]);
            const uint32_t a1 = __float_as_uint(sPw[(g + 8) * STRP + kb * 8 + tig]);
            const uint32_t a2 = __float_as_uint(sPw[g * STRP + kb * 8 + tig + 4]);
            const uint32_t a3 = __float_as_uint(sPw[(g + 8) * STRP + kb * 8 + tig + 4]);
#pragma unroll
            for (int nb = 0; nb < 8; nb++) {
                const float* vp = sV + (kb * 8 + tig) * STRV + nb * 8 + g;
                mma_tf32(o[nb], a0, a1, a2, a3,
                         __float_as_uint(vp[0]),
                         __float_as_uint(vp[4 * STRV]));
            }
        }
        __syncwarp();   // all lanes done reading sPw before next tile's stores
    }

    // ---- finalize -----------------------------------------------------------
    const float inv0 = 1.f / l0;
    const float inv1 = 1.f / l1;
    float* Og = O + (size_t)bn * kT * kD;
#pragma unroll
    for (int nb = 0; nb < 8; nb++) {
        *(float2*)(Og + (size_t)rowg0 * kD + nb * 8 + 2 * tig) =
            make_float2(o[nb][0] * inv0, o[nb][1] * inv0);
        *(float2*)(Og + (size_t)rowg1 * kD + nb * 8 + 2 * tig) =
            make_float2(o[nb][2] * inv1, o[nb][3] * inv1);
    }
}

extern "C" void kernel_launch(void* const* d_in, const int* in_sizes, int n_in,
                              void* d_out, int out_size) {
    const float* q = (const float*)d_in[0];
    const float* k = (const float*)d_in[1];
    const float* v = (const float*)d_in[2];
    float* o = (float*)d_out;

    const size_t smem_bytes = (size_t)SMEM_FLOATS * sizeof(float);
    cudaFuncSetAttribute(attn_tf32_kernel,
                         cudaFuncAttributeMaxDynamicSharedMemorySize,
                         (int)smem_bytes);

    dim3 grid(kT / BM, 64);   // 16 q-tiles x 64 batch-heads
    attn_tf32_kernel<<<grid, THREADS, smem_bytes>>>(q, k, v, o);
}